// round 12
// baseline (speedup 1.0000x reference)
#include <cuda_runtime.h>
#include <math.h>

// Problem constants
#define T_STEPS 16384
#define HID     1024
#define INP     256
#define NLAB    32

#define NCTA    64           // persistent CTAs
#define WPC     8            // warps per CTA
#define TPB     (WPC * 32)   // 256
#define RPW     2            // rows per warp; NCTA*WPC*RPW == HID

// Hidden state words: fp32 h with mantissa LSB = 1-bit step tag
// tau(s) = (s>>1)&1. Double-buffered by parity s&1; stale content is from
// step s-2 whose tau differs -> LSB equality == ready. Naturally-aligned 4B
// accesses are single-copy atomic (value+tag never tear); validity is
// in-word, so no fences anywhere. LSB clobber <= 2^-23 relative (absorbed by
// the contractive recurrence). Reset restores both buffers every launch.
__device__ unsigned g_hbuf[2][HID];

__device__ __forceinline__ uint4 ldv4(const unsigned* p) {
    uint4 v;
    asm volatile("ld.relaxed.gpu.global.v4.u32 {%0,%1,%2,%3}, [%4];"
                 : "=r"(v.x), "=r"(v.y), "=r"(v.z), "=r"(v.w) : "l"(p));
    return v;
}
__device__ __forceinline__ void stx32(unsigned* p, unsigned v) {
    asm volatile("st.relaxed.gpu.global.u32 [%0], %1;" :: "l"(p), "r"(v) : "memory");
}
__device__ __forceinline__ float tanh_fast(float v) {
    float r;
    asm volatile("tanh.approx.f32 %0, %1;" : "=f"(r) : "f"(v));
    return r;
}
__device__ __forceinline__ unsigned readyv(uint4 v, unsigned tau) {
    return ((((v.x ^ tau) | (v.y ^ tau) | (v.z ^ tau) | (v.w ^ tau)) & 1u) == 0u);
}

__global__ void rnn_reset_kernel() {
    int t = threadIdx.x;
    for (int i = t; i < HID; i += blockDim.x) {
        g_hbuf[0][i] = 0u;   // h0 = 0.0f, LSB 0 == tau(0): valid for step 0
        g_hbuf[1][i] = 1u;   // LSB 1 != tau(1)=0: step-1 consumers must wait
    }
}

__global__ void __launch_bounds__(TPB, 1) rnn_scan_kernel(
    const float* __restrict__ X,    // [T, 1, 256]
    const float* __restrict__ Wi,   // [1024, 256]
    const float* __restrict__ bi,   // [1024]
    const float* __restrict__ bh,   // [1024]  (note: param order fixed below)
    const float* __restrict__ Wh,   // [1024, 1024]
    const float* __restrict__ Wo,   // [32, 1024]
    const float* __restrict__ bo,   // [32]
    float* __restrict__ out)        // [32] log-softmax
{
    const int t    = threadIdx.x;
    const int lane = t & 31;
    const int warp = t >> 5;
    const int r0   = blockIdx.x * (WPC * RPW) + 2 * warp;  // this warp's rows
    const int r1   = r0 + 1;

    // ---- Register-resident weights (held for all 16384 steps) ----
    // Lane l owns h columns [32l, 32l+32): one contiguous 128B span -> 8x v4
    // global polls feed both rows' FMAs directly from registers.
    float w0[32], w1[32];
    #pragma unroll
    for (int k = 0; k < 32; k++) {
        int col = 32 * lane + k;
        w0[k] = Wh[r0 * HID + col];
        w1[k] = Wh[r1 * HID + col];
    }
    // Lane l owns input columns [8l, 8l+8).
    float wi0[8], wi1[8];
    #pragma unroll
    for (int k = 0; k < 8; k++) {
        int col = 8 * lane + k;
        wi0[k] = Wi[r0 * INP + col];
        wi1[k] = Wi[r1 * INP + col];
    }
    const float bias0 = bi[r0] + bh[r0];
    const float bias1 = bi[r1] + bh[r1];

    // ---- Input pipeline: x0 = step s, x1 = step s+1 (8 floats per lane) ----
    const float4* X4 = (const float4*)X;   // step s at X4[s*64 + 2*lane + {0,1}]
    float4 x0a = X4[2 * lane];         float4 x0b = X4[2 * lane + 1];
    float4 x1a = X4[64 + 2 * lane];    float4 x1b = X4[64 + 2 * lane + 1];

    for (int s = 0; s < T_STEPS; s++) {
        const int buf = s & 1;
        const unsigned tau = ((unsigned)s >> 1) & 1u;
        const unsigned* hp = g_hbuf[buf] + 32 * lane;

        // ---- Issue all 8 independent polls up front (pipelined). ----
        uint4 v[8];
        #pragma unroll
        for (int i = 0; i < 8; i++) v[i] = ldv4(hp + 4 * i);

        // Prefetch x for step s+2 while polls are in flight.
        float4 x2a, x2b;
        x2a.x = x2a.y = x2a.z = x2a.w = 0.f;
        x2b = x2a;
        if (s + 2 < T_STEPS) {
            x2a = X4[(s + 2) * 64 + 2 * lane];
            x2b = X4[(s + 2) * 64 + 2 * lane + 1];
        }

        // Input projection for THIS step (both rows share x).
        float a0 = (lane == 0) ? bias0 : 0.0f;
        float a1 = 0.f, a2 = 0.f, a3 = 0.f;
        float b0 = (lane == 0) ? bias1 : 0.0f;
        float b1 = 0.f, b2 = 0.f, b3 = 0.f;
        a0 = fmaf(wi0[0], x0a.x, a0);  a1 = fmaf(wi0[1], x0a.y, a1);
        a2 = fmaf(wi0[2], x0a.z, a2);  a3 = fmaf(wi0[3], x0a.w, a3);
        a0 = fmaf(wi0[4], x0b.x, a0);  a1 = fmaf(wi0[5], x0b.y, a1);
        a2 = fmaf(wi0[6], x0b.z, a2);  a3 = fmaf(wi0[7], x0b.w, a3);
        b0 = fmaf(wi1[0], x0a.x, b0);  b1 = fmaf(wi1[1], x0a.y, b1);
        b2 = fmaf(wi1[2], x0a.z, b2);  b3 = fmaf(wi1[3], x0a.w, b3);
        b0 = fmaf(wi1[4], x0b.x, b0);  b1 = fmaf(wi1[5], x0b.y, b1);
        b2 = fmaf(wi1[6], x0b.z, b2);  b3 = fmaf(wi1[7], x0b.w, b3);

        // ---- Dataflow consume: FMA each 4-word group as it becomes ready;
        // re-poll only pending groups. No barrier, no SMEM staging. ----
        unsigned pend = 0xFFu;
        do {
            #pragma unroll
            for (int i = 0; i < 8; i++) {
                if (pend & (1u << i)) {
                    if (readyv(v[i], tau)) {
                        float hx = __uint_as_float(v[i].x);
                        float hy = __uint_as_float(v[i].y);
                        float hz = __uint_as_float(v[i].z);
                        float hw = __uint_as_float(v[i].w);
                        a0 = fmaf(w0[4 * i + 0], hx, a0);
                        a1 = fmaf(w0[4 * i + 1], hy, a1);
                        a2 = fmaf(w0[4 * i + 2], hz, a2);
                        a3 = fmaf(w0[4 * i + 3], hw, a3);
                        b0 = fmaf(w1[4 * i + 0], hx, b0);
                        b1 = fmaf(w1[4 * i + 1], hy, b1);
                        b2 = fmaf(w1[4 * i + 2], hz, b2);
                        b3 = fmaf(w1[4 * i + 3], hw, b3);
                        pend &= ~(1u << i);
                    } else {
                        v[i] = ldv4(hp + 4 * i);
                    }
                }
            }
        } while (pend);

        float accA = (a0 + a1) + (a2 + a3);
        float accB = (b0 + b1) + (b2 + b3);

        // Two interleaved butterflies (ILP; all lanes get both sums).
        #pragma unroll
        for (int off = 16; off > 0; off >>= 1) {
            accA += __shfl_xor_sync(0xffffffffu, accA, off);
            accB += __shfl_xor_sync(0xffffffffu, accB, off);
        }

        // Parallel publish: lane 0 -> r0, lane 1 -> r1 (coalesced pair).
        const unsigned ntau = (((unsigned)(s + 1)) >> 1) & 1u;
        if (lane < 2) {
            float hnew = tanh_fast(lane == 0 ? accA : accB);
            unsigned ub = (__float_as_uint(hnew) & ~1u) | ntau;
            stx32(&g_hbuf[buf ^ 1][r0 + lane], ub);
        }

        x0a = x1a; x0b = x1b;
        x1a = x2a; x1b = x2b;
    }

    // ---- Epilogue: CTA 0 computes logits + log_softmax on h_T ----
    if (blockIdx.x == 0) {
        __shared__ float shE[HID];
        const unsigned tauT = ((unsigned)T_STEPS >> 1) & 1u;   // buffer 0
        for (int j = t; j < HID; j += TPB) {
            unsigned vv;
            do {
                asm volatile("ld.relaxed.gpu.global.u32 %0, [%1];"
                             : "=r"(vv) : "l"(&g_hbuf[0][j]));
            } while ((vv & 1u) != tauT);
            shE[j] = __uint_as_float(vv);
        }
        __syncthreads();

        int orow = t >> 3;      // 32 rows x 8 threads
        int sub  = t & 7;
        float acc = 0.0f;
        #pragma unroll 4
        for (int j = 0; j < HID / 8; j += 4) {
            int col = sub * (HID / 8) + j;
            float4 w4 = ((const float4*)Wo)[(orow * HID + col) >> 2];
            acc = fmaf(w4.x, shE[col + 0], acc);
            acc = fmaf(w4.y, shE[col + 1], acc);
            acc = fmaf(w4.z, shE[col + 2], acc);
            acc = fmaf(w4.w, shE[col + 3], acc);
        }
        acc += __shfl_down_sync(0xffffffffu, acc, 4);
        acc += __shfl_down_sync(0xffffffffu, acc, 2);
        acc += __shfl_down_sync(0xffffffffu, acc, 1);

        __shared__ float s_log[NLAB];
        if (sub == 0) s_log[orow] = acc + bo[orow];
        __syncthreads();

        if (t < NLAB) {
            float vl = s_log[t];
            float m = vl;
            #pragma unroll
            for (int off = 16; off > 0; off >>= 1)
                m = fmaxf(m, __shfl_xor_sync(0xffffffffu, m, off));
            float e = expf(vl - m);
            float ssum = e;
            #pragma unroll
            for (int off = 16; off > 0; off >>= 1)
                ssum += __shfl_xor_sync(0xffffffffu, ssum, off);
            out[t] = vl - m - logf(ssum);
        }
    }
}

extern "C" void kernel_launch(void* const* d_in, const int* in_sizes, int n_in,
                              void* d_out, int out_size) {
    const float* X  = (const float*)d_in[0];
    const float* Wi = (const float*)d_in[1];
    const float* bi = (const float*)d_in[2];
    const float* Wh = (const float*)d_in[3];
    const float* bh = (const float*)d_in[4];
    const float* Wo = (const float*)d_in[5];
    const float* bo = (const float*)d_in[6];
    float* out = (float*)d_out;

    rnn_reset_kernel<<<1, 256>>>();
    // NOTE: kernel signature order is (X, Wi, bi, bh, Wh, Wo, bo, out)
    rnn_scan_kernel<<<NCTA, TPB>>>(X, Wi, bi, bh, Wh, Wo, bo, out);
}

// round 13
// speedup vs baseline: 1.7722x; 1.7722x over previous
#include <cuda_runtime.h>
#include <math.h>

// Problem constants
#define T_STEPS 16384
#define HID     1024
#define INP     256
#define NLAB    32

#define NCTA    64           // persistent CTAs
#define WPC     8            // warps per CTA
#define TPB     (WPC * 32)   // 256
#define RPW     2            // rows per warp; NCTA*WPC*RPW == HID

// Hidden state words: fp32 h with mantissa LSB = 1-bit step tag
// tau(s) = (s>>1)&1. Double-buffered by parity s&1; stale content is from
// step s-2 whose tau differs -> LSB equality == ready. Naturally-aligned 4B
// accesses are single-copy atomic EVERYWHERE (global and shared), so
// value+tag can never tear and validity is in-word: no fences, and (new this
// round) no per-step __syncthreads. LSB clobber <= 2^-23 relative (absorbed
// by the contractive recurrence). Reset restores both buffers every launch.
__device__ unsigned g_hbuf[2][HID];

__device__ __forceinline__ uint4 ldv4g(const unsigned* p) {
    uint4 v;
    asm volatile("ld.volatile.global.v4.u32 {%0,%1,%2,%3}, [%4];"
                 : "=r"(v.x), "=r"(v.y), "=r"(v.z), "=r"(v.w) : "l"(p));
    return v;
}
__device__ __forceinline__ void stx32(unsigned* p, unsigned v) {
    asm volatile("st.relaxed.gpu.global.u32 [%0], %1;" :: "l"(p), "r"(v) : "memory");
}
__device__ __forceinline__ uint4 ldv4s(unsigned a) {
    uint4 v;
    asm volatile("ld.volatile.shared.v4.u32 {%0,%1,%2,%3}, [%4];"
                 : "=r"(v.x), "=r"(v.y), "=r"(v.z), "=r"(v.w) : "r"(a));
    return v;
}
__device__ __forceinline__ void stv4s(unsigned a, uint4 v) {
    asm volatile("st.volatile.shared.v4.u32 [%0], {%1,%2,%3,%4};"
                 :: "r"(a), "r"(v.x), "r"(v.y), "r"(v.z), "r"(v.w) : "memory");
}
__device__ __forceinline__ float tanh_fast(float v) {
    float r;
    asm volatile("tanh.approx.f32 %0, %1;" : "=f"(r) : "f"(v));
    return r;
}
__device__ __forceinline__ unsigned notready(uint4 v, unsigned tau) {
    return ((v.x ^ tau) | (v.y ^ tau) | (v.z ^ tau) | (v.w ^ tau)) & 1u;
}

__global__ void rnn_reset_kernel() {
    int t = threadIdx.x;
    for (int i = t; i < HID; i += blockDim.x) {
        g_hbuf[0][i] = 0u;   // h0 = 0.0f, LSB 0 == tau(0): valid for step 0
        g_hbuf[1][i] = 1u;   // LSB 1 != tau(1)=0: step-1 consumers must wait
    }
}

__global__ void __launch_bounds__(TPB, 1) rnn_scan_kernel(
    const float* __restrict__ X,    // [T, 1, 256]
    const float* __restrict__ Wi,   // [1024, 256]
    const float* __restrict__ bi,   // [1024]
    const float* __restrict__ Wh,   // [1024, 1024]
    const float* __restrict__ bh,   // [1024]
    const float* __restrict__ Wo,   // [32, 1024]
    const float* __restrict__ bo,   // [32]
    float* __restrict__ out)        // [32] log-softmax
{
    const int t    = threadIdx.x;
    const int lane = t & 31;
    const int warp = t >> 5;
    const int r0   = blockIdx.x * (WPC * RPW) + 2 * warp;  // this warp's rows
    const int r1   = r0 + 1;

    // Double-buffered LSB-tagged h staged per CTA (dataflow, no barrier).
    __shared__ unsigned stag[2][HID];
    __shared__ float shE[HID];   // epilogue scratch

    // Sentinel (odd LSB) so step-0/1 consumers never accept garbage.
    for (int i = t; i < 2 * HID; i += TPB)
        ((unsigned*)stag)[i] = 1u;

    // ---- Register-resident weights (held for all 16384 steps) ----
    // Consume slot g covers column group pg=(warp+g)&7, cols pg*128+4l+(0..3).
    // Slot g=0 is this warp's OWN fill group (consumed from registers).
    float w0[32], w1[32];
    #pragma unroll
    for (int g = 0; g < 8; g++) {
        int pg = (warp + g) & 7;
        #pragma unroll
        for (int j = 0; j < 4; j++) {
            int col = pg * 128 + 4 * lane + j;
            w0[4 * g + j] = Wh[r0 * HID + col];
            w1[4 * g + j] = Wh[r1 * HID + col];
        }
    }
    float wi0[8], wi1[8];
    #pragma unroll
    for (int k = 0; k < 8; k++) {
        int col = (k >> 2) * 128 + 4 * lane + (k & 3);
        wi0[k] = Wi[r0 * INP + col];
        wi1[k] = Wi[r1 * INP + col];
    }
    const float bias0 = bi[r0] + bh[r0];
    const float bias1 = bi[r1] + bh[r1];

    __syncthreads();   // sentinel init visible (once, pre-loop)

    // ---- 3-deep input pipeline: x0 = step s, x1 = step s+1 ----
    const float4* X4 = (const float4*)X;   // step s slice at X4[s*64 + ...]
    float4 x0a = X4[lane];            float4 x0b = X4[32 + lane];
    float4 x1a = X4[64 + lane];       float4 x1b = X4[96 + lane];

    const unsigned sbase = (unsigned)__cvta_generic_to_shared(&stag[0][0]);

    for (int s = 0; s < T_STEPS; s++) {
        const int buf = s & 1;
        const unsigned tau = ((unsigned)s >> 1) & 1u;
        const unsigned* hp = g_hbuf[buf] + 4 * t;   // own 4 contiguous words
        const unsigned sb = sbase + (unsigned)buf * (HID * 4);

        // ---- Poll: one v4 load covers this thread's 4 words. ----
        uint4 v = ldv4g(hp);

        // Prefetch x for step s+2 (two step-periods of DRAM cover).
        float4 x2a, x2b;
        x2a.x = x2a.y = x2a.z = x2a.w = 0.f;
        x2b = x2a;
        if (s + 2 < T_STEPS) {
            x2a = X4[(s + 2) * 64 + lane];
            x2b = X4[(s + 2) * 64 + 32 + lane];
        }

        // Input projection for THIS step (both rows) while poll is in flight.
        float a0 = (lane == 0) ? bias0 : 0.0f;
        float a1 = 0.f, a2 = 0.f, a3 = 0.f;
        float b0 = (lane == 0) ? bias1 : 0.0f;
        float b1 = 0.f, b2 = 0.f, b3 = 0.f;
        a0 = fmaf(wi0[0], x0a.x, a0);  a1 = fmaf(wi0[1], x0a.y, a1);
        a2 = fmaf(wi0[2], x0a.z, a2);  a3 = fmaf(wi0[3], x0a.w, a3);
        a0 = fmaf(wi0[4], x0b.x, a0);  a1 = fmaf(wi0[5], x0b.y, a1);
        a2 = fmaf(wi0[6], x0b.z, a2);  a3 = fmaf(wi0[7], x0b.w, a3);
        b0 = fmaf(wi1[0], x0a.x, b0);  b1 = fmaf(wi1[1], x0a.y, b1);
        b2 = fmaf(wi1[2], x0a.z, b2);  b3 = fmaf(wi1[3], x0a.w, b3);
        b0 = fmaf(wi1[4], x0b.x, b0);  b1 = fmaf(wi1[5], x0b.y, b1);
        b2 = fmaf(wi1[6], x0b.z, b2);  b3 = fmaf(wi1[7], x0b.w, b3);

        // Spin: re-issue the v4 until all 4 LSBs match tau, then deposit.
        while (notready(v, tau)) v = ldv4g(hp);
        stv4s(sb + 16 * (unsigned)t, v);   // warp w fills group w

        // ---- Consume slot 0 = own group, straight from registers. ----
        {
            float hx = __uint_as_float(v.x), hy = __uint_as_float(v.y);
            float hz = __uint_as_float(v.z), hw = __uint_as_float(v.w);
            a0 = fmaf(w0[0], hx, a0);  a1 = fmaf(w0[1], hy, a1);
            a2 = fmaf(w0[2], hz, a2);  a3 = fmaf(w0[3], hw, a3);
            b0 = fmaf(w1[0], hx, b0);  b1 = fmaf(w1[1], hy, b1);
            b2 = fmaf(w1[2], hz, b2);  b3 = fmaf(w1[3], hw, b3);
        }

        // ---- Slots 1..7: spin on SMEM group (volatile LDS.128, each 4B
        // element atomic), FMA as soon as ready. Rotation avoids convoy. ----
        #pragma unroll
        for (int g = 1; g < 8; g++) {
            int pg = (warp + g) & 7;
            unsigned a = sb + (unsigned)(pg * 128 + 4 * lane) * 4u;
            uint4 h;
            do { h = ldv4s(a); } while (notready(h, tau));
            float hx = __uint_as_float(h.x), hy = __uint_as_float(h.y);
            float hz = __uint_as_float(h.z), hw = __uint_as_float(h.w);
            a0 = fmaf(w0[4 * g + 0], hx, a0);
            a1 = fmaf(w0[4 * g + 1], hy, a1);
            a2 = fmaf(w0[4 * g + 2], hz, a2);
            a3 = fmaf(w0[4 * g + 3], hw, a3);
            b0 = fmaf(w1[4 * g + 0], hx, b0);
            b1 = fmaf(w1[4 * g + 1], hy, b1);
            b2 = fmaf(w1[4 * g + 2], hz, b2);
            b3 = fmaf(w1[4 * g + 3], hw, b3);
        }

        float accA = (a0 + a1) + (a2 + a3);
        float accB = (b0 + b1) + (b2 + b3);

        // Two interleaved butterflies (ILP; all lanes get both sums).
        #pragma unroll
        for (int off = 16; off > 0; off >>= 1) {
            accA += __shfl_xor_sync(0xffffffffu, accA, off);
            accB += __shfl_xor_sync(0xffffffffu, accB, off);
        }

        // Parallel publish: lane 0 -> r0, lane 1 -> r1 (coalesced pair).
        const unsigned ntau = (((unsigned)(s + 1)) >> 1) & 1u;
        if (lane < 2) {
            float hnew = tanh_fast(lane == 0 ? accA : accB);
            unsigned ub = (__float_as_uint(hnew) & ~1u) | ntau;
            stx32(&g_hbuf[buf ^ 1][r0 + lane], ub);
        }

        x0a = x1a; x0b = x1b;
        x1a = x2a; x1b = x2b;
    }

    // ---- Epilogue: CTA 0 computes logits + log_softmax on h_T ----
    if (blockIdx.x == 0) {
        const unsigned tauT = ((unsigned)T_STEPS >> 1) & 1u;   // buffer 0
        for (int j = t; j < HID; j += TPB) {
            unsigned vv;
            do {
                asm volatile("ld.volatile.global.u32 %0, [%1];"
                             : "=r"(vv) : "l"(&g_hbuf[0][j]));
            } while ((vv & 1u) != tauT);
            shE[j] = __uint_as_float(vv);
        }
        __syncthreads();

        int orow = t >> 3;      // 32 rows x 8 threads
        int sub  = t & 7;
        float acc = 0.0f;
        #pragma unroll 4
        for (int j = 0; j < HID / 8; j += 4) {
            int col = sub * (HID / 8) + j;
            float4 w4 = ((const float4*)Wo)[(orow * HID + col) >> 2];
            acc = fmaf(w4.x, shE[col + 0], acc);
            acc = fmaf(w4.y, shE[col + 1], acc);
            acc = fmaf(w4.z, shE[col + 2], acc);
            acc = fmaf(w4.w, shE[col + 3], acc);
        }
        acc += __shfl_down_sync(0xffffffffu, acc, 4);
        acc += __shfl_down_sync(0xffffffffu, acc, 2);
        acc += __shfl_down_sync(0xffffffffu, acc, 1);

        __shared__ float s_log[NLAB];
        if (sub == 0) s_log[orow] = acc + bo[orow];
        __syncthreads();

        if (t < NLAB) {
            float vl = s_log[t];
            float m = vl;
            #pragma unroll
            for (int off = 16; off > 0; off >>= 1)
                m = fmaxf(m, __shfl_xor_sync(0xffffffffu, m, off));
            float e = expf(vl - m);
            float ssum = e;
            #pragma unroll
            for (int off = 16; off > 0; off >>= 1)
                ssum += __shfl_xor_sync(0xffffffffu, ssum, off);
            out[t] = vl - m - logf(ssum);
        }
    }
}

extern "C" void kernel_launch(void* const* d_in, const int* in_sizes, int n_in,
                              void* d_out, int out_size) {
    const float* X  = (const float*)d_in[0];
    const float* Wi = (const float*)d_in[1];
    const float* bi = (const float*)d_in[2];
    const float* Wh = (const float*)d_in[3];
    const float* bh = (const float*)d_in[4];
    const float* Wo = (const float*)d_in[5];
    const float* bo = (const float*)d_in[6];
    float* out = (float*)d_out;

    rnn_reset_kernel<<<1, 256>>>();
    rnn_scan_kernel<<<NCTA, TPB>>>(X, Wi, bi, Wh, bh, Wo, bo, out);
}

// round 14
// speedup vs baseline: 6.5178x; 3.6779x over previous
#include <cuda_runtime.h>
#include <math.h>

// Problem constants
#define T_STEPS 16384
#define HID     1024
#define INP     256
#define NLAB    32

#define NCTA    128          // persistent CTAs, one per SM, single wave
#define WPC     8            // warps per CTA; NCTA*WPC == HID rows (1 warp : 1 row)
#define TPB     (WPC * 32)   // 256
#define WPT     (HID / TPB)  // tagged words polled per thread = 4
#define NREP    3            // publication replicas (phase-staggered poll chains)

// Tagged hidden state: word = (float_bits(h) << 32) | step_tag, written to
// NREP replica addresses. Double-buffered by step parity; each relaxed 64-bit
// store publishes value+tag atomically -> no fences anywhere. Consumers run
// one dependent-load chain per replica with ~80-cycle phase offsets, so the
// effective publication-detect sampling period is RTT/NREP instead of RTT.
__device__ unsigned long long g_hbuf[2][NREP][HID];

__device__ __forceinline__ unsigned long long ldx(const unsigned long long* p) {
    unsigned long long v;
    asm volatile("ld.relaxed.gpu.global.b64 %0, [%1];" : "=l"(v) : "l"(p));
    return v;
}
__device__ __forceinline__ void stx(unsigned long long* p, unsigned long long v) {
    asm volatile("st.relaxed.gpu.global.b64 [%0], %1;" :: "l"(p), "l"(v) : "memory");
}
__device__ __forceinline__ unsigned long long packh(float h, unsigned tag) {
    return ((unsigned long long)__float_as_uint(h) << 32) | (unsigned long long)tag;
}
__device__ __forceinline__ float unpackh(unsigned long long v) {
    return __uint_as_float((unsigned)(v >> 32));
}
__device__ __forceinline__ float tanh_fast(float v) {
    float r;
    asm volatile("tanh.approx.f32 %0, %1;" : "=f"(r) : "f"(v));
    return r;
}
__device__ __forceinline__ unsigned clk32() {
    unsigned c;
    asm volatile("mov.u32 %0, %%clock;" : "=r"(c));
    return c;
}
// ~10x4-cycle dependent ALU chain; output is runtime-opaque to the compiler.
__device__ __forceinline__ unsigned lcg_chain(unsigned d) {
    #pragma unroll
    for (int i = 0; i < 10; i++) d = d * 1664525u + 1013904223u;
    return d;
}

__global__ void rnn_reset_kernel() {
    int t = threadIdx.x;
    unsigned long long z = packh(0.0f, 0u);   // h0 = 0, tag 0
    for (int i = t; i < 2 * NREP * HID; i += blockDim.x)
        ((unsigned long long*)g_hbuf)[i] = z;
}

__global__ void __launch_bounds__(TPB, 1) rnn_scan_kernel(
    const float* __restrict__ X,    // [T, 1, 256]
    const float* __restrict__ Wi,   // [1024, 256]
    const float* __restrict__ bi,   // [1024]
    const float* __restrict__ Wh,   // [1024, 1024]
    const float* __restrict__ bh,   // [1024]
    const float* __restrict__ Wo,   // [32, 1024]
    const float* __restrict__ bo,   // [32]
    float* __restrict__ out)        // [32] log-softmax
{
    const int t    = threadIdx.x;
    const int lane = t & 31;
    const int warp = t >> 5;
    const int row  = blockIdx.x * WPC + warp;   // this warp's hidden row

    // Double-buffered plain-float h staged per CTA. One barrier per step.
    __shared__ float sh[2][HID];

    // ---- Register-resident weights (held for all 16384 steps) ----
    float w[32];
    #pragma unroll
    for (int k = 0; k < 32; k++)
        w[k] = Wh[row * HID + (k >> 2) * 128 + 4 * lane + (k & 3)];
    float wi[8];
    #pragma unroll
    for (int k = 0; k < 8; k++)
        wi[k] = Wi[row * INP + (k >> 2) * 128 + 4 * lane + (k & 3)];
    const float bias = bi[row] + bh[row];

    // ---- 3-deep input pipeline: x0 = step s, x1 = step s+1 ----
    const float4* X4 = (const float4*)X;
    float4 x0a = X4[lane];            float4 x0b = X4[32 + lane];
    float4 x1a = X4[64 + lane];       float4 x1b = X4[96 + lane];

    for (int s = 0; s < T_STEPS; s++) {
        const int buf = s & 1;
        const unsigned tag = (unsigned)s;
        const unsigned long long* hb0 = g_hbuf[buf][0];
        const unsigned long long* hb1 = g_hbuf[buf][1];
        const unsigned long long* hb2 = g_hbuf[buf][2];

        // ---- Chain 0: issue all 4 replica-0 polls immediately. ----
        unsigned long long v0[WPT], v1[WPT], v2[WPT];
        #pragma unroll
        for (int i = 0; i < WPT; i++) v0[i] = ldx(hb0 + t + TPB * i);

        // Prefetch x for step s+2 (two step-periods of DRAM cover).
        float4 x2a, x2b;
        x2a.x = x2a.y = x2a.z = x2a.w = 0.f;
        x2b = x2a;
        if (s + 2 < T_STEPS) {
            x2a = X4[(s + 2) * 64 + lane];
            x2b = X4[(s + 2) * 64 + 32 + lane];
        }

        // Input projection for THIS step while chain-0 polls are in flight.
        float a0 = (lane == 0) ? bias : 0.0f;
        float a1 = 0.f, a2 = 0.f, a3 = 0.f;
        a0 = fmaf(wi[0], x0a.x, a0);  a1 = fmaf(wi[1], x0a.y, a1);
        a2 = fmaf(wi[2], x0a.z, a2);  a3 = fmaf(wi[3], x0a.w, a3);
        a0 = fmaf(wi[4], x0b.x, a0);  a1 = fmaf(wi[5], x0b.y, a1);
        a2 = fmaf(wi[6], x0b.z, a2);  a3 = fmaf(wi[7], x0b.w, a3);

        // ---- Chains 1 and 2: issue ~80 / ~160 cycles later. The gating
        // predicates are always-true in practice but runtime-opaque, forcing
        // a real dependency on the delay chains (timing only — if ever
        // false, the stale sample is simply retried next round). ----
        unsigned d1 = lcg_chain(clk32() ^ __float_as_uint(a0));
        if (d1 != 0x9E3779B9u) {
            #pragma unroll
            for (int i = 0; i < WPT; i++) v1[i] = ldx(hb1 + t + TPB * i);
        }
        unsigned d2 = lcg_chain(d1);
        if (d2 != 0x9E3779B9u) {
            #pragma unroll
            for (int i = 0; i < WPT; i++) v2[i] = ldx(hb2 + t + TPB * i);
        }

        // ---- Phase-staggered spin: three phases per round, each checking
        // and re-issuing only ITS chain; LCG delay chains keep the phases
        // ~80 cycles apart so publication is detected within ~RTT/3. ----
        unsigned pend = (1u << WPT) - 1u;
        for (;;) {
            // phase 0
            #pragma unroll
            for (int i = 0; i < WPT; i++)
                if ((pend & (1u << i)) && (unsigned)v0[i] == tag) {
                    sh[buf][t + TPB * i] = unpackh(v0[i]);
                    pend &= ~(1u << i);
                }
            if (!pend) break;
            {
                unsigned dd = lcg_chain((unsigned)v0[0] ^ (unsigned)v0[3]);
                if (dd != 0x85EBCA6Bu) {
                    #pragma unroll
                    for (int i = 0; i < WPT; i++)
                        if (pend & (1u << i)) v0[i] = ldx(hb0 + t + TPB * i);
                }
                // phase 1
                #pragma unroll
                for (int i = 0; i < WPT; i++)
                    if ((pend & (1u << i)) && (unsigned)v1[i] == tag) {
                        sh[buf][t + TPB * i] = unpackh(v1[i]);
                        pend &= ~(1u << i);
                    }
                if (!pend) break;
                unsigned de = lcg_chain(dd ^ (unsigned)v1[0]);
                if (de != 0xC2B2AE35u) {
                    #pragma unroll
                    for (int i = 0; i < WPT; i++)
                        if (pend & (1u << i)) v1[i] = ldx(hb1 + t + TPB * i);
                }
                // phase 2
                #pragma unroll
                for (int i = 0; i < WPT; i++)
                    if ((pend & (1u << i)) && (unsigned)v2[i] == tag) {
                        sh[buf][t + TPB * i] = unpackh(v2[i]);
                        pend &= ~(1u << i);
                    }
                if (!pend) break;
                unsigned df = lcg_chain(de ^ (unsigned)v2[0]);
                if (df != 0x27D4EB2Fu) {
                    #pragma unroll
                    for (int i = 0; i < WPT; i++)
                        if (pend & (1u << i)) v2[i] = ldx(hb2 + t + TPB * i);
                }
            }
        }

        __syncthreads();   // the only barrier per step

        // ---- Recurrent GEMV: 8x LDS.128 + 32 FMA (exact R5 path). ----
        const float* hs = sh[buf];
        #pragma unroll
        for (int g = 0; g < 8; g++) {
            float4 h4 = *(const float4*)(hs + g * 128 + 4 * lane);
            a0 = fmaf(w[4 * g + 0], h4.x, a0);
            a1 = fmaf(w[4 * g + 1], h4.y, a1);
            a2 = fmaf(w[4 * g + 2], h4.z, a2);
            a3 = fmaf(w[4 * g + 3], h4.w, a3);
        }
        float acc = (a0 + a1) + (a2 + a3);
        #pragma unroll
        for (int off = 16; off > 0; off >>= 1)
            acc += __shfl_xor_sync(0xffffffffu, acc, off);

        if (lane == 0) {
            float hnew = tanh_fast(acc);
            unsigned long long pv = packh(hnew, tag + 1u);
            stx(&g_hbuf[buf ^ 1][0][row], pv);
            stx(&g_hbuf[buf ^ 1][1][row], pv);
            stx(&g_hbuf[buf ^ 1][2][row], pv);
        }

        x0a = x1a; x0b = x1b;
        x1a = x2a; x1b = x2b;
    }

    // ---- Epilogue: CTA 0 computes logits + log_softmax on h_T ----
    if (blockIdx.x == 0) {
        for (int j = t; j < HID; j += TPB) {
            unsigned long long vv = ldx(&g_hbuf[0][0][j]);   // T even -> buffer 0
            while (((unsigned)vv) != (unsigned)T_STEPS) vv = ldx(&g_hbuf[0][0][j]);
            sh[0][j] = unpackh(vv);
        }
        __syncthreads();

        int orow = t >> 3;      // 32 rows x 8 threads
        int sub  = t & 7;
        float acc = 0.0f;
        #pragma unroll 4
        for (int j = 0; j < HID / 8; j += 4) {
            int col = sub * (HID / 8) + j;
            float4 w4 = ((const float4*)Wo)[(orow * HID + col) >> 2];
            acc = fmaf(w4.x, sh[0][col + 0], acc);
            acc = fmaf(w4.y, sh[0][col + 1], acc);
            acc = fmaf(w4.z, sh[0][col + 2], acc);
            acc = fmaf(w4.w, sh[0][col + 3], acc);
        }
        acc += __shfl_down_sync(0xffffffffu, acc, 4);
        acc += __shfl_down_sync(0xffffffffu, acc, 2);
        acc += __shfl_down_sync(0xffffffffu, acc, 1);

        __shared__ float s_log[NLAB];
        if (sub == 0) s_log[orow] = acc + bo[orow];
        __syncthreads();

        if (t < NLAB) {
            float vl = s_log[t];
            float m = vl;
            #pragma unroll
            for (int off = 16; off > 0; off >>= 1)
                m = fmaxf(m, __shfl_xor_sync(0xffffffffu, m, off));
            float e = expf(vl - m);
            float ssum = e;
            #pragma unroll
            for (int off = 16; off > 0; off >>= 1)
                ssum += __shfl_xor_sync(0xffffffffu, ssum, off);
            out[t] = vl - m - logf(ssum);
        }
    }
}

extern "C" void kernel_launch(void* const* d_in, const int* in_sizes, int n_in,
                              void* d_out, int out_size) {
    const float* X  = (const float*)d_in[0];
    const float* Wi = (const float*)d_in[1];
    const float* bi = (const float*)d_in[2];
    const float* Wh = (const float*)d_in[3];
    const float* bh = (const float*)d_in[4];
    const float* Wo = (const float*)d_in[5];
    const float* bo = (const float*)d_in[6];
    float* out = (float*)d_out;

    rnn_reset_kernel<<<1, 1024>>>();
    rnn_scan_kernel<<<NCTA, TPB>>>(X, Wi, bi, Wh, bh, Wo, bo, out);
}

// round 15
// speedup vs baseline: 10.2241x; 1.5686x over previous
#include <cuda_runtime.h>
#include <math.h>

// Problem constants
#define T_STEPS 16384
#define HID     1024
#define INP     256
#define NLAB    32

#define NCTA    128          // persistent CTAs, one per SM, single wave
#define WPC     8            // warps per CTA; NCTA*WPC == HID rows (1 warp : 1 row)
#define TPB     (WPC * 32)   // 256
#define WPT     (HID / TPB)  // tagged words polled per thread = 4

// Tagged hidden state: word = (float_bits(h) << 32) | step_tag.
// Double-buffered by step parity; a single relaxed 64-bit store publishes
// value+tag atomically -> no fences anywhere. Reset kernel restores tags each
// launch so graph replays are deterministic. (R5 protocol, proven.)
__device__ unsigned long long g_hbuf[2][HID];

__device__ __forceinline__ unsigned long long ldx(const unsigned long long* p) {
    unsigned long long v;
    asm volatile("ld.relaxed.gpu.global.b64 %0, [%1];" : "=l"(v) : "l"(p));
    return v;
}
__device__ __forceinline__ void stx(unsigned long long* p, unsigned long long v) {
    asm volatile("st.relaxed.gpu.global.b64 [%0], %1;" :: "l"(p), "l"(v) : "memory");
}
__device__ __forceinline__ unsigned long long packh(float h, unsigned tag) {
    return ((unsigned long long)__float_as_uint(h) << 32) | (unsigned long long)tag;
}
__device__ __forceinline__ float unpackh(unsigned long long v) {
    return __uint_as_float((unsigned)(v >> 32));
}
__device__ __forceinline__ float tanh_fast(float v) {
    float r;
    asm volatile("tanh.approx.f32 %0, %1;" : "=f"(r) : "f"(v));
    return r;
}

__global__ void rnn_reset_kernel() {
    int t = threadIdx.x;
    unsigned long long z = packh(0.0f, 0u);   // h0 = 0, tag 0
    for (int i = t; i < 2 * HID; i += blockDim.x)
        ((unsigned long long*)g_hbuf)[i] = z;
}

__global__ void __launch_bounds__(TPB, 1) rnn_scan_kernel(
    const float* __restrict__ X,    // [T, 1, 256]
    const float* __restrict__ Wi,   // [1024, 256]
    const float* __restrict__ bi,   // [1024]
    const float* __restrict__ Wh,   // [1024, 1024]
    const float* __restrict__ bh,   // [1024]
    const float* __restrict__ Wo,   // [32, 1024]
    const float* __restrict__ bo,   // [32]
    float* __restrict__ out)        // [32] log-softmax
{
    const int t    = threadIdx.x;
    const int lane = t & 31;
    const int warp = t >> 5;
    const int row  = blockIdx.x * WPC + warp;   // this warp's hidden row

    // Double-buffered plain-float h staged per CTA. Two barriers per step
    // (split-half pipeline): GEMV on cols [0,512) overlaps the straggler
    // tail of cols [512,1024).
    __shared__ float sh[2][HID];

    // ---- Register-resident weights (held for all 16384 steps) ----
    // Lane l owns hidden columns (k/4)*128 + 4l + (k%4), k=0..31 (float4-
    // contiguous groups -> 8x LDS.128 per step); groups 0-3 cover cols
    // [0,512), groups 4-7 cover [512,1024).
    float w[32];
    #pragma unroll
    for (int k = 0; k < 32; k++)
        w[k] = Wh[row * HID + (k >> 2) * 128 + 4 * lane + (k & 3)];
    float wi[8];
    #pragma unroll
    for (int k = 0; k < 8; k++)
        wi[k] = Wi[row * INP + (k >> 2) * 128 + 4 * lane + (k & 3)];
    const float bias = bi[row] + bh[row];

    // ---- 3-deep input pipeline: x0 = step s, x1 = step s+1 ----
    const float4* X4 = (const float4*)X;   // step s slice at X4[s*64 + ...]
    float4 x0a = X4[lane];            float4 x0b = X4[32 + lane];
    float4 x1a = X4[64 + lane];       float4 x1b = X4[96 + lane];

    for (int s = 0; s < T_STEPS; s++) {
        const int buf = s & 1;
        const unsigned tag = (unsigned)s;
        const unsigned long long* hb = g_hbuf[buf];

        // ---- Issue ALL 4 polls up front (halves resolve concurrently). ----
        // Words t, t+256 lie in cols [0,512); words t+512, t+768 in [512,1024).
        unsigned long long v0 = ldx(hb + t);
        unsigned long long v1 = ldx(hb + t + TPB);
        unsigned long long v2 = ldx(hb + t + 2 * TPB);
        unsigned long long v3 = ldx(hb + t + 3 * TPB);

        // Prefetch x for step s+2 (two step-periods of DRAM cover).
        float4 x2a, x2b;
        x2a.x = x2a.y = x2a.z = x2a.w = 0.f;
        x2b = x2a;
        if (s + 2 < T_STEPS) {
            x2a = X4[(s + 2) * 64 + lane];
            x2b = X4[(s + 2) * 64 + 32 + lane];
        }

        // Input projection for THIS step while polls are in flight.
        float a0 = (lane == 0) ? bias : 0.0f;
        float a1 = 0.f, a2 = 0.f, a3 = 0.f;
        a0 = fmaf(wi[0], x0a.x, a0);  a1 = fmaf(wi[1], x0a.y, a1);
        a2 = fmaf(wi[2], x0a.z, a2);  a3 = fmaf(wi[3], x0a.w, a3);
        a0 = fmaf(wi[4], x0b.x, a0);  a1 = fmaf(wi[5], x0b.y, a1);
        a2 = fmaf(wi[6], x0b.z, a2);  a3 = fmaf(wi[7], x0b.w, a3);

        // ---- Spin on FIRST half only; second-half polls stay in flight. ----
        while ((((unsigned)v0) ^ tag) | (((unsigned)v1) ^ tag)) {
            if ((unsigned)v0 != tag) v0 = ldx(hb + t);
            if ((unsigned)v1 != tag) v1 = ldx(hb + t + TPB);
        }
        sh[buf][t]       = unpackh(v0);
        sh[buf][t + TPB] = unpackh(v1);

        __syncthreads();   // barrier 1: cols [0,512) staged

        // ---- GEMV-A on cols [0,512) — overlaps second-half straggler tail.
        const float* hs = sh[buf];
        #pragma unroll
        for (int g = 0; g < 4; g++) {
            float4 h4 = *(const float4*)(hs + g * 128 + 4 * lane);
            a0 = fmaf(w[4 * g + 0], h4.x, a0);
            a1 = fmaf(w[4 * g + 1], h4.y, a1);
            a2 = fmaf(w[4 * g + 2], h4.z, a2);
            a3 = fmaf(w[4 * g + 3], h4.w, a3);
        }

        // ---- Spin on SECOND half (usually already resolved). ----
        while ((((unsigned)v2) ^ tag) | (((unsigned)v3) ^ tag)) {
            if ((unsigned)v2 != tag) v2 = ldx(hb + t + 2 * TPB);
            if ((unsigned)v3 != tag) v3 = ldx(hb + t + 3 * TPB);
        }
        sh[buf][t + 2 * TPB] = unpackh(v2);
        sh[buf][t + 3 * TPB] = unpackh(v3);

        __syncthreads();   // barrier 2: cols [512,1024) staged

        // ---- GEMV-B on cols [512,1024). ----
        #pragma unroll
        for (int g = 4; g < 8; g++) {
            float4 h4 = *(const float4*)(hs + g * 128 + 4 * lane);
            a0 = fmaf(w[4 * g + 0], h4.x, a0);
            a1 = fmaf(w[4 * g + 1], h4.y, a1);
            a2 = fmaf(w[4 * g + 2], h4.z, a2);
            a3 = fmaf(w[4 * g + 3], h4.w, a3);
        }
        float acc = (a0 + a1) + (a2 + a3);
        #pragma unroll
        for (int off = 16; off > 0; off >>= 1)
            acc += __shfl_xor_sync(0xffffffffu, acc, off);

        if (lane == 0) {
            float hnew = tanh_fast(acc);
            stx(&g_hbuf[buf ^ 1][row], packh(hnew, tag + 1u));
        }

        x0a = x1a; x0b = x1b;
        x1a = x2a; x1b = x2b;
    }

    // ---- Epilogue: CTA 0 computes logits + log_softmax on h_T ----
    if (blockIdx.x == 0) {
        for (int j = t; j < HID; j += TPB) {
            unsigned long long vv = ldx(&g_hbuf[0][j]);   // T even -> buffer 0
            while (((unsigned)vv) != (unsigned)T_STEPS) vv = ldx(&g_hbuf[0][j]);
            sh[0][j] = unpackh(vv);
        }
        __syncthreads();

        int orow = t >> 3;      // 32 rows x 8 threads
        int sub  = t & 7;
        float acc = 0.0f;
        #pragma unroll 4
        for (int j = 0; j < HID / 8; j += 4) {
            int col = sub * (HID / 8) + j;
            float4 w4 = ((const float4*)Wo)[(orow * HID + col) >> 2];
            acc = fmaf(w4.x, sh[0][col + 0], acc);
            acc = fmaf(w4.y, sh[0][col + 1], acc);
            acc = fmaf(w4.z, sh[0][col + 2], acc);
            acc = fmaf(w4.w, sh[0][col + 3], acc);
        }
        acc += __shfl_down_sync(0xffffffffu, acc, 4);
        acc += __shfl_down_sync(0xffffffffu, acc, 2);
        acc += __shfl_down_sync(0xffffffffu, acc, 1);

        __shared__ float s_log[NLAB];
        if (sub == 0) s_log[orow] = acc + bo[orow];
        __syncthreads();

        if (t < NLAB) {
            float vl = s_log[t];
            float m = vl;
            #pragma unroll
            for (int off = 16; off > 0; off >>= 1)
                m = fmaxf(m, __shfl_xor_sync(0xffffffffu, m, off));
            float e = expf(vl - m);
            float ssum = e;
            #pragma unroll
            for (int off = 16; off > 0; off >>= 1)
                ssum += __shfl_xor_sync(0xffffffffu, ssum, off);
            out[t] = vl - m - logf(ssum);
        }
    }
}

extern "C" void kernel_launch(void* const* d_in, const int* in_sizes, int n_in,
                              void* d_out, int out_size) {
    const float* X  = (const float*)d_in[0];
    const float* Wi = (const float*)d_in[1];
    const float* bi = (const float*)d_in[2];
    const float* Wh = (const float*)d_in[3];
    const float* bh = (const float*)d_in[4];
    const float* Wo = (const float*)d_in[5];
    const float* bo = (const float*)d_in[6];
    float* out = (float*)d_out;

    rnn_reset_kernel<<<1, 256>>>();
    rnn_scan_kernel<<<NCTA, TPB>>>(X, Wi, bi, Wh, bh, Wo, bo, out);
}

// round 16
// speedup vs baseline: 11.5784x; 1.1325x over previous
#include <cuda_runtime.h>
#include <math.h>

// Problem constants
#define T_STEPS 16384
#define HID     1024
#define INP     256
#define NLAB    32

#define NCTA    128          // persistent CTAs, one per SM, single wave
#define WPC     8            // warps per CTA; NCTA*WPC == HID rows (1 warp : 1 row)
#define TPB     (WPC * 32)   // 256
#define WPT     (HID / TPB)  // tagged words polled per thread = 4

// Tagged hidden state: word = (float_bits(h) << 32) | step_tag.
// Double-buffered by step parity; a single relaxed 64-bit store publishes
// value+tag atomically -> no fences anywhere. Reset kernel restores tags each
// launch so graph replays are deterministic. (R5 protocol, proven.)
// R16 tweak: polls for step s+1 are issued BEFORE step s's reduce/publish,
// so poll issue + first RTT are off the serial chain. Pre-publish samples
// return stale tags (<= s-1) and are retried by the existing loop.
__device__ unsigned long long g_hbuf[2][HID];

__device__ __forceinline__ unsigned long long ldx(const unsigned long long* p) {
    unsigned long long v;
    asm volatile("ld.relaxed.gpu.global.b64 %0, [%1];" : "=l"(v) : "l"(p));
    return v;
}
__device__ __forceinline__ void stx(unsigned long long* p, unsigned long long v) {
    asm volatile("st.relaxed.gpu.global.b64 [%0], %1;" :: "l"(p), "l"(v) : "memory");
}
__device__ __forceinline__ unsigned long long packh(float h, unsigned tag) {
    return ((unsigned long long)__float_as_uint(h) << 32) | (unsigned long long)tag;
}
__device__ __forceinline__ float unpackh(unsigned long long v) {
    return __uint_as_float((unsigned)(v >> 32));
}
__device__ __forceinline__ float tanh_fast(float v) {
    float r;
    asm volatile("tanh.approx.f32 %0, %1;" : "=f"(r) : "f"(v));
    return r;
}

__global__ void rnn_reset_kernel() {
    int t = threadIdx.x;
    unsigned long long z = packh(0.0f, 0u);   // h0 = 0, tag 0
    for (int i = t; i < 2 * HID; i += blockDim.x)
        ((unsigned long long*)g_hbuf)[i] = z;
}

__global__ void __launch_bounds__(TPB, 1) rnn_scan_kernel(
    const float* __restrict__ X,    // [T, 1, 256]
    const float* __restrict__ Wi,   // [1024, 256]
    const float* __restrict__ bi,   // [1024]
    const float* __restrict__ Wh,   // [1024, 1024]
    const float* __restrict__ bh,   // [1024]
    const float* __restrict__ Wo,   // [32, 1024]
    const float* __restrict__ bo,   // [32]
    float* __restrict__ out)        // [32] log-softmax
{
    const int t    = threadIdx.x;
    const int lane = t & 31;
    const int warp = t >> 5;
    const int row  = blockIdx.x * WPC + warp;   // this warp's hidden row

    // Double-buffered plain-float h staged per CTA. One barrier per step.
    __shared__ float sh[2][HID];

    // ---- Register-resident weights (held for all 16384 steps) ----
    // Lane l owns hidden columns (k/4)*128 + 4l + (k%4), k=0..31 (float4-
    // contiguous groups -> 8x LDS.128 per step) and the analogous 8 input cols.
    float w[32];
    #pragma unroll
    for (int k = 0; k < 32; k++)
        w[k] = Wh[row * HID + (k >> 2) * 128 + 4 * lane + (k & 3)];
    float wi[8];
    #pragma unroll
    for (int k = 0; k < 8; k++)
        wi[k] = Wi[row * INP + (k >> 2) * 128 + 4 * lane + (k & 3)];
    const float bias = bi[row] + bh[row];

    // ---- 3-deep input pipeline: x0 = step s, x1 = step s+1 ----
    const float4* X4 = (const float4*)X;   // step s slice at X4[s*64 + ...]
    float4 x0a = X4[lane];            float4 x0b = X4[32 + lane];
    float4 x1a = X4[64 + lane];       float4 x1b = X4[96 + lane];

    // ---- Pipeline prologue: issue polls for step 0 (buffer 0). ----
    unsigned long long v[WPT];
    #pragma unroll
    for (int i = 0; i < WPT; i++) v[i] = ldx(g_hbuf[0] + t + TPB * i);

    for (int s = 0; s < T_STEPS; s++) {
        const int buf = s & 1;
        const unsigned tag = (unsigned)s;
        const unsigned long long* hb = g_hbuf[buf];

        // Prefetch x for step s+2 (two step-periods of DRAM cover).
        float4 x2a, x2b;
        x2a.x = x2a.y = x2a.z = x2a.w = 0.f;
        x2b = x2a;
        if (s + 2 < T_STEPS) {
            x2a = X4[(s + 2) * 64 + lane];
            x2b = X4[(s + 2) * 64 + 32 + lane];
        }

        // Input projection for THIS step while polls are in flight.
        float a0 = (lane == 0) ? bias : 0.0f;
        float a1 = 0.f, a2 = 0.f, a3 = 0.f;
        a0 = fmaf(wi[0], x0a.x, a0);  a1 = fmaf(wi[1], x0a.y, a1);
        a2 = fmaf(wi[2], x0a.z, a2);  a3 = fmaf(wi[3], x0a.w, a3);
        a0 = fmaf(wi[4], x0b.x, a0);  a1 = fmaf(wi[5], x0b.y, a1);
        a2 = fmaf(wi[6], x0b.z, a2);  a3 = fmaf(wi[7], x0b.w, a3);

        // Resolve tags: retry only stale words (tags monotone, <= s).
        for (;;) {
            unsigned bad = 0;
            #pragma unroll
            for (int i = 0; i < WPT; i++) bad |= ((unsigned)v[i]) ^ tag;
            if (bad == 0) break;
            #pragma unroll
            for (int i = 0; i < WPT; i++)
                if (((unsigned)v[i]) != tag) v[i] = ldx(hb + t + TPB * i);
        }
        #pragma unroll
        for (int i = 0; i < WPT; i++) sh[buf][t + TPB * i] = unpackh(v[i]);

        __syncthreads();   // the only barrier per step

        // ---- R16 tweak: issue step-s+1 polls NOW (buffer buf^1), before
        // the reduce/publish — poll issue + first RTT leave the serial
        // chain. Stale samples (tag <= s-1) are retried next iteration. ----
        const unsigned long long* hbn = g_hbuf[buf ^ 1];
        #pragma unroll
        for (int i = 0; i < WPT; i++) v[i] = ldx(hbn + t + TPB * i);

        // ---- Recurrent GEMV: 8x LDS.128 + 32 FMA. ----
        const float* hs = sh[buf];
        #pragma unroll
        for (int g = 0; g < 8; g++) {
            float4 h4 = *(const float4*)(hs + g * 128 + 4 * lane);
            a0 = fmaf(w[4 * g + 0], h4.x, a0);
            a1 = fmaf(w[4 * g + 1], h4.y, a1);
            a2 = fmaf(w[4 * g + 2], h4.z, a2);
            a3 = fmaf(w[4 * g + 3], h4.w, a3);
        }
        float acc = (a0 + a1) + (a2 + a3);
        #pragma unroll
        for (int off = 16; off > 0; off >>= 1)
            acc += __shfl_xor_sync(0xffffffffu, acc, off);

        if (lane == 0) {
            float hnew = tanh_fast(acc);
            stx(&g_hbuf[buf ^ 1][row], packh(hnew, tag + 1u));
        }

        x0a = x1a; x0b = x1b;
        x1a = x2a; x1b = x2b;
    }

    // ---- Epilogue: CTA 0 computes logits + log_softmax on h_T ----
    if (blockIdx.x == 0) {
        for (int j = t; j < HID; j += TPB) {
            unsigned long long vv = ldx(&g_hbuf[0][j]);   // T even -> buffer 0
            while (((unsigned)vv) != (unsigned)T_STEPS) vv = ldx(&g_hbuf[0][j]);
            sh[0][j] = unpackh(vv);
        }
        __syncthreads();

        int orow = t >> 3;      // 32 rows x 8 threads
        int sub  = t & 7;
        float acc = 0.0f;
        #pragma unroll 4
        for (int j = 0; j < HID / 8; j += 4) {
            int col = sub * (HID / 8) + j;
            float4 w4 = ((const float4*)Wo)[(orow * HID + col) >> 2];
            acc = fmaf(w4.x, sh[0][col + 0], acc);
            acc = fmaf(w4.y, sh[0][col + 1], acc);
            acc = fmaf(w4.z, sh[0][col + 2], acc);
            acc = fmaf(w4.w, sh[0][col + 3], acc);
        }
        acc += __shfl_down_sync(0xffffffffu, acc, 4);
        acc += __shfl_down_sync(0xffffffffu, acc, 2);
        acc += __shfl_down_sync(0xffffffffu, acc, 1);

        __shared__ float s_log[NLAB];
        if (sub == 0) s_log[orow] = acc + bo[orow];
        __syncthreads();

        if (t < NLAB) {
            float vl = s_log[t];
            float m = vl;
            #pragma unroll
            for (int off = 16; off > 0; off >>= 1)
                m = fmaxf(m, __shfl_xor_sync(0xffffffffu, m, off));
            float e = expf(vl - m);
            float ssum = e;
            #pragma unroll
            for (int off = 16; off > 0; off >>= 1)
                ssum += __shfl_xor_sync(0xffffffffu, ssum, off);
            out[t] = vl - m - logf(ssum);
        }
    }
}

extern "C" void kernel_launch(void* const* d_in, const int* in_sizes, int n_in,
                              void* d_out, int out_size) {
    const float* X  = (const float*)d_in[0];
    const float* Wi = (const float*)d_in[1];
    const float* bi = (const float*)d_in[2];
    const float* Wh = (const float*)d_in[3];
    const float* bh = (const float*)d_in[4];
    const float* Wo = (const float*)d_in[5];
    const float* bo = (const float*)d_in[6];
    float* out = (float*)d_out;

    rnn_reset_kernel<<<1, 256>>>();
    rnn_scan_kernel<<<NCTA, TPB>>>(X, Wi, bi, Wh, bh, Wo, bo, out);
}